// round 17
// baseline (speedup 1.0000x reference)
#include <cuda_runtime.h>

#define BN 128
#define TN 512
#define HN 256
#define G4N 1024
typedef unsigned long long ULL;

__device__ __forceinline__ ULL pack2(float x, float y){ULL r;asm("mov.b64 %0,{%1,%2};":"=l"(r):"f"(x),"f"(y));return r;}
__device__ __forceinline__ void unpack2(ULL v,float&x,float&y){asm("mov.b64 {%0,%1},%2;":"=f"(x),"=f"(y):"l"(v));}
__device__ __forceinline__ ULL fma2(ULL a,ULL b,ULL c){ULL d;asm("fma.rn.f32x2 %0,%1,%2,%3;":"=l"(d):"l"(a),"l"(b),"l"(c));return d;}
__device__ __forceinline__ unsigned smem_u32(const void* p){ return (unsigned)__cvta_generic_to_shared(p); }
__device__ __forceinline__ void cp16(unsigned dst, const void* src){
    asm volatile("cp.async.cg.shared.global [%0], [%1], 16;\n" :: "r"(dst), "l"(src) : "memory");
}
__device__ __forceinline__ void cp_commit(){ asm volatile("cp.async.commit_group;\n":::"memory"); }
__device__ __forceinline__ void cp_wait0(){ asm volatile("cp.async.wait_group 0;\n":::"memory"); }
__device__ __forceinline__ void cp_wait1(){ asm volatile("cp.async.wait_group 1;\n":::"memory"); }

// activations mirroring the R9 forms that measured rel_err 5.9e-7:
// tanh = (1-e)/(1+e), e = exp(-2|x|); division via Newton-refined rcp (~1e-7)
__device__ __forceinline__ float ex2_ap(float x){float y;asm("ex2.approx.f32 %0,%1;":"=f"(y):"f"(x));return y;}
__device__ __forceinline__ float rcp_rf(float d){
    float r; asm("rcp.approx.f32 %0,%1;":"=f"(r):"f"(d));
    return r*(2.0f - d*r);                       // one Newton step
}
__device__ __forceinline__ float fast_tanh(float x){
    float ax=fabsf(x);
    float e =ex2_ap(-2.8853900817779268f*ax);    // exp(-2ax)
    float r =(1.0f-e)*rcp_rf(1.0f+e);
    return (x>=0.0f)?r:-r;
}
__device__ __forceinline__ float fast_sigmoid(float x){ return fmaf(fast_tanh(0.5f*x),0.5f,0.5f); }

// ---- scratch (static __device__) ----
__device__ __align__(16) float g_h0[TN*BN*512];          // layer0 out [t][b][2H]
__device__ __align__(16) float g_gx1[2u*TN*BN*G4N];      // layer1 gate inputs [dir][t][b][n*4+gate]
__device__ __align__(16) ULL   g_hd[2*HN*BN];            // dup-packed h, [dir][n][b]
__device__ __align__(16) float g_pool[BN*512];           // mean_t h1 [b][2H]
__device__ unsigned g_cnt [2][8][2];
__device__ unsigned g_flag[2][8][2];
__device__ unsigned g_done[16];

__global__ void init_kernel(){
    int i=threadIdx.x;
    if(i<32) ((unsigned*)g_cnt)[i]=0u;
    else if(i<64) ((unsigned*)g_flag)[i-32]=0u;
    else if(i<80) g_done[i-64]=0u;
}

// ---- scan dynamic smem (bytes) ----
#define SM_W    0                        // float [256][64]  wh^T (i,f,g,o per unit) 65536
#define SM_H2   65536                    // ULL   [256][34]  dup h (k-major)          69632
#define SM_BS   (SM_H2+256*34*8)         // float [64]       bias (gate-major)          256
#define SM_WI0  (SM_BS+256)              // float [64][4]                              1024
#define SM_TOT  (SM_WI0+1024)            // 136448

template<int LAYER>
__global__ void __launch_bounds__(256,1) lstm_scan_kernel(
    const float* __restrict__ x, const float* __restrict__ w_ih0,
    const float* __restrict__ w_hh, const float* __restrict__ b_ih,
    const float* __restrict__ b_hh)
{
    extern __shared__ char smem[];
    float* w_s    = (float*)(smem+SM_W);
    ULL*   h2_s   = (ULL*)  (smem+SM_H2);
    float* bsum_s = (float*)(smem+SM_BS);
    float* wi0_s  = (float*)(smem+SM_WI0);
    const unsigned h2_base = smem_u32(h2_s);

    const int bx=blockIdx.x, dir=bx>>6, cc=bx&63;
    const int btile=cc>>4, ntile=cc&15, tx=threadIdx.x;
    const int grp = dir*4 + btile;

    // one-time staging: w_s[k][nn*4+gate] (NON-dup, float)
    for(int i=tx;i<64*256;i+=256){
        int jl=i>>8, k=i&255, nn=jl>>2, gate=jl&3;
        int row=gate*256+ntile*16+nn;
        w_s[k*64+jl]=w_hh[(dir*G4N+row)*HN+k];
    }
    for(int jl=tx;jl<64;jl+=256){
        int nn=jl>>2, gate=jl&3, row=gate*256+ntile*16+nn;
        bsum_s[jl]=b_ih[dir*G4N+row]+b_hh[dir*G4N+row];
        if(LAYER==0){
            #pragma unroll
            for(int d=0;d<4;d++) wi0_s[jl*4+d]=w_ih0[(dir*G4N+row)*4+d];
        }
    }

    // warp mapping: 4 units x 8 batch-pairs per warp (2 smem wavefronts per k)
    const int wq=tx>>5;
    const int nn=(wq&3)*4 + (tx&3);
    const int bp=(wq>>2)*8 + ((tx>>2)&7);
    const int n=ntile*16+nn, b0=bp*2, bglob0=btile*32;
    float c0=0.f,c1=0.f,s0=0.f,s1=0.f;

    float4 pf0, pf1, npf0, npf1;
    {
        int t0 = dir ? TN-1 : 0;
        if(LAYER==0){
            npf0 = *(const float4*)&x[((bglob0+b0  )*TN + t0)*4];
            npf1 = *(const float4*)&x[((bglob0+b0+1)*TN + t0)*4];
        } else {
            const long gb=((long)(dir*TN+t0)*BN)*G4N;
            npf0 = *(const float4*)&g_gx1[gb + (long)(bglob0+b0  )*G4N + n*4];
            npf1 = *(const float4*)&g_gx1[gb + (long)(bglob0+b0+1)*G4N + n*4];
        }
    }
    pf0=npf0; pf1=npf1;
    __syncthreads();   // staging done

    for(int s=0;s<TN;s++){
        const int t = dir ? (TN-1-s) : s;

        // gate pre-activation bases: pairs (i,f) and (g,o) per batch
        float ba0[4], ba1[4];
        if(LAYER==0){
            #pragma unroll
            for(int g=0;g<4;g++){
                int jl=nn*4+g;
                ba0[g]=bsum_s[jl]+wi0_s[jl*4+0]*pf0.x+wi0_s[jl*4+1]*pf0.y
                                 +wi0_s[jl*4+2]*pf0.z+wi0_s[jl*4+3]*pf0.w;
                ba1[g]=bsum_s[jl]+wi0_s[jl*4+0]*pf1.x+wi0_s[jl*4+1]*pf1.y
                                 +wi0_s[jl*4+2]*pf1.z+wi0_s[jl*4+3]*pf1.w;
            }
        } else {
            ba0[0]=pf0.x+bsum_s[nn*4+0]; ba0[1]=pf0.y+bsum_s[nn*4+1];
            ba0[2]=pf0.z+bsum_s[nn*4+2]; ba0[3]=pf0.w+bsum_s[nn*4+3];
            ba1[0]=pf1.x+bsum_s[nn*4+0]; ba1[1]=pf1.y+bsum_s[nn*4+1];
            ba1[2]=pf1.z+bsum_s[nn*4+2]; ba1[3]=pf1.w+bsum_s[nn*4+3];
        }
        ULL aif0=pack2(ba0[0],ba0[1]), ago0=pack2(ba0[2],ba0[3]);   // batch b0: (i,f),(g,o)
        ULL aif1=pack2(ba1[0],ba1[1]), ago1=pack2(ba1[2],ba1[3]);   // batch b0+1

        // prefetch next step's gate inputs (no h dependency)
        if(s+1<TN){
            int tn = dir ? (t-1) : (t+1);
            if(LAYER==0){
                npf0 = *(const float4*)&x[((bglob0+b0  )*TN + tn)*4];
                npf1 = *(const float4*)&x[((bglob0+b0+1)*TN + tn)*4];
            } else {
                const long gb=((long)(dir*TN+tn)*BN)*G4N;
                npf0 = *(const float4*)&g_gx1[gb + (long)(bglob0+b0  )*G4N + n*4];
                npf1 = *(const float4*)&g_gx1[gb + (long)(bglob0+b0+1)*G4N + n*4];
            }
        }

        // recurrent GEMM: per k = 2xLDS.128 + 4xFFMA2 (crossbar-balanced)
        if(s>0){
            cp_wait1();  __syncthreads();      // first half of h tile landed
            const ULL* wp=(const ULL*)(w_s + nn*4);   // (w_i,w_f),(w_g,w_o) pairs
            const ULL* hp=h2_s + b0;                  // dup h pair base
            #pragma unroll 8
            for(int k=0;k<128;k++){
                ulonglong2 hh=*(const ulonglong2*)(hp + k*34);    // dup(h[b0]), dup(h[b0+1])
                ulonglong2 ww=*(const ulonglong2*)(wp + k*32);    // (wi,wf),(wg,wo)
                aif0=fma2(ww.x,hh.x,aif0); ago0=fma2(ww.y,hh.x,ago0);
                aif1=fma2(ww.x,hh.y,aif1); ago1=fma2(ww.y,hh.y,ago1);
            }
            cp_wait0(); __syncthreads();
            #pragma unroll 8
            for(int k=128;k<256;k++){
                ulonglong2 hh=*(const ulonglong2*)(hp + k*34);
                ulonglong2 ww=*(const ulonglong2*)(wp + k*32);
                aif0=fma2(ww.x,hh.x,aif0); ago0=fma2(ww.y,hh.x,ago0);
                aif1=fma2(ww.x,hh.y,aif1); ago1=fma2(ww.y,hh.y,ago1);
            }
        }

        // cell update entirely in registers
        {
            float gi0,gf0,gg0,go0,gi1,gf1,gg1,go1;
            unpack2(aif0,gi0,gf0); unpack2(ago0,gg0,go0);
            unpack2(aif1,gi1,gf1); unpack2(ago1,gg1,go1);
            c0 = fast_sigmoid(gf0)*c0 + fast_sigmoid(gi0)*fast_tanh(gg0);
            c1 = fast_sigmoid(gf1)*c1 + fast_sigmoid(gi1)*fast_tanh(gg1);
            float h0v = fast_sigmoid(go0)*fast_tanh(c0);
            float h1v = fast_sigmoid(go1)*fast_tanh(c1);
            ULL d0=pack2(h0v,h0v), d1=pack2(h1v,h1v);
            asm volatile("st.global.cg.v2.u64 [%0],{%1,%2};"
                         :: "l"(&g_hd[(dir*HN+n)*BN + bglob0+b0]), "l"(d0), "l"(d1) : "memory");
            if(LAYER==0){
                g_h0[((t*BN)+bglob0+b0  )*512+dir*256+n]=h0v;
                g_h0[((t*BN)+bglob0+b0+1)*512+dir*256+n]=h1v;
            } else { s0+=h0v; s1+=h1v; }
        }
        pf0=npf0; pf1=npf1;

        if(s+1<TN){
            __syncthreads();
            if(tx==0){
                const int p=s&1; const unsigned target=(unsigned)(s+1);
                __threadfence();
                unsigned old=atomicAdd(&g_cnt[LAYER][grp][p],1u);
                if(old==15u){
                    g_cnt[LAYER][grp][p]=0u;
                    __threadfence();
                    atomicExch(&g_flag[LAYER][grp][p], target);
                } else {
                    while((int)(__ldcg(&g_flag[LAYER][grp][p]) - target) < 0) { }
                    __threadfence();
                }
            }
            __syncthreads();
            // async-copy next dup-h tile (64KB), two groups (k<128 | k>=128)
            const ULL* src=&g_hd[(dir*HN)*BN + bglob0];
            for(int i=tx;i<2048;i+=256){
                int kk=i>>4, c2=(i&15)*2;
                cp16(h2_base + (unsigned)((kk*34+c2)*8), src + kk*BN + c2);
            }
            cp_commit();
            for(int i=tx;i<2048;i+=256){
                int kk=128+(i>>4), c2=(i&15)*2;
                cp16(h2_base + (unsigned)((kk*34+c2)*8), src + kk*BN + c2);
            }
            cp_commit();
        }
    }

    // end-of-launch barrier-state reset (also makes ncu kernel-replay passes sane)
    __syncthreads();
    if(tx==0){
        unsigned old=atomicAdd(&g_done[LAYER*8+grp],1u);
        if(old==15u){
            g_done[LAYER*8+grp]=0u;
            g_flag[LAYER][grp][0]=0u; g_flag[LAYER][grp][1]=0u;
            __threadfence();
        }
    }

    if(LAYER==1){
        const float inv=1.0f/(float)TN;
        g_pool[(bglob0+b0  )*512+dir*256+n]=s0*inv;
        g_pool[(bglob0+b0+1)*512+dir*256+n]=s1*inv;
    }
}

// ---------------------------------------------------------------------------
// gx1 = h0cat @ w_ih1^T, output columns permuted to n*4+gate.
// M=65536, N'=1024/dir, K=512. CTA 128m x 128j, thread 8m x 8j, f32x2.
// ---------------------------------------------------------------------------
#define GX_A   0                    // ULL [32][130]  dup A   33280
#define GX_B   33280                // float [32][132] B      16896
#define GX_SM  (GX_A+33280+16896)

__global__ void __launch_bounds__(256,2) gx1_gemm_kernel(const float* __restrict__ w_ih1)
{
    extern __shared__ char smg[];
    ULL*   A2  = (ULL*)(smg+GX_A);
    ULL*   Bu  = (ULL*)(smg+GX_B);
    float* Bf  = (float*)Bu;

    const int dir=blockIdx.x>>3, jt=blockIdx.x&7, mt=blockIdx.y, tx=threadIdx.x;
    const int jgrp=tx&15, mgrp=tx>>4;
    const int j0=jgrp*8, m0=mgrp*8;
    const int mbase=mt*128, jbase=jt*128;

    ULL acc[8][4];
    #pragma unroll
    for(int i=0;i<8;i++)
        #pragma unroll
        for(int j=0;j<4;j++) acc[i][j]=0ull;

    for(int kc=0;kc<512;kc+=32){
        for(int i=tx;i<4096;i+=256){                  // A: 128m x 32k, dup-pack
            int mm=i>>5, kk=i&31;
            float v=g_h0[(mbase+mm)*512+kc+kk];
            A2[kk*130+mm]=pack2(v,v);
        }
        for(int i=tx;i<4096;i+=256){                  // B: permuted rows N'=n*4+g
            int jj=i>>5, kk=i&31;
            int np=jbase+jj, row=(np&3)*256+(np>>2);
            Bf[kk*132+jj]=w_ih1[((dir*G4N)+row)*512+kc+kk];
        }
        __syncthreads();
        const ULL* ap=A2+m0;
        const ULL* bp=Bu+(j0>>1);
        #pragma unroll 8
        for(int k=0;k<32;k++){
            ulonglong2 a01=*(const ulonglong2*)(ap+k*130);
            ulonglong2 a23=*(const ulonglong2*)(ap+k*130+2);
            ulonglong2 a45=*(const ulonglong2*)(ap+k*130+4);
            ulonglong2 a67=*(const ulonglong2*)(ap+k*130+6);
            ulonglong2 b01=*(const ulonglong2*)(bp+k*66);
            ulonglong2 b23=*(const ulonglong2*)(bp+k*66+2);
            acc[0][0]=fma2(b01.x,a01.x,acc[0][0]); acc[0][1]=fma2(b01.y,a01.x,acc[0][1]);
            acc[0][2]=fma2(b23.x,a01.x,acc[0][2]); acc[0][3]=fma2(b23.y,a01.x,acc[0][3]);
            acc[1][0]=fma2(b01.x,a01.y,acc[1][0]); acc[1][1]=fma2(b01.y,a01.y,acc[1][1]);
            acc[1][2]=fma2(b23.x,a01.y,acc[1][2]); acc[1][3]=fma2(b23.y,a01.y,acc[1][3]);
            acc[2][0]=fma2(b01.x,a23.x,acc[2][0]); acc[2][1]=fma2(b01.y,a23.x,acc[2][1]);
            acc[2][2]=fma2(b23.x,a23.x,acc[2][2]); acc[2][3]=fma2(b23.y,a23.x,acc[2][3]);
            acc[3][0]=fma2(b01.x,a23.y,acc[3][0]); acc[3][1]=fma2(b01.y,a23.y,acc[3][1]);
            acc[3][2]=fma2(b23.x,a23.y,acc[3][2]); acc[3][3]=fma2(b23.y,a23.y,acc[3][3]);
            acc[4][0]=fma2(b01.x,a45.x,acc[4][0]); acc[4][1]=fma2(b01.y,a45.x,acc[4][1]);
            acc[4][2]=fma2(b23.x,a45.x,acc[4][2]); acc[4][3]=fma2(b23.y,a45.x,acc[4][3]);
            acc[5][0]=fma2(b01.x,a45.y,acc[5][0]); acc[5][1]=fma2(b01.y,a45.y,acc[5][1]);
            acc[5][2]=fma2(b23.x,a45.y,acc[5][2]); acc[5][3]=fma2(b23.y,a45.y,acc[5][3]);
            acc[6][0]=fma2(b01.x,a67.x,acc[6][0]); acc[6][1]=fma2(b01.y,a67.x,acc[6][1]);
            acc[6][2]=fma2(b23.x,a67.x,acc[6][2]); acc[6][3]=fma2(b23.y,a67.x,acc[6][3]);
            acc[7][0]=fma2(b01.x,a67.y,acc[7][0]); acc[7][1]=fma2(b01.y,a67.y,acc[7][1]);
            acc[7][2]=fma2(b23.x,a67.y,acc[7][2]); acc[7][3]=fma2(b23.y,a67.y,acc[7][3]);
        }
        __syncthreads();
    }

    #pragma unroll
    for(int i=0;i<8;i++){
        int m=mbase+m0+i, t=m>>7, b=m&127;
        float* dst=&g_gx1[(((long)dir*TN+t)*BN+b)*G4N+jbase+j0];
        float l0,h0_,l1,h1_;
        unpack2(acc[i][0],l0,h0_); unpack2(acc[i][1],l1,h1_);
        *(float4*)dst = make_float4(l0,h0_,l1,h1_);
        unpack2(acc[i][2],l0,h0_); unpack2(acc[i][3],l1,h1_);
        *(float4*)(dst+4) = make_float4(l0,h0_,l1,h1_);
    }
}

__global__ void fc_kernel(const float* __restrict__ fc_w, const float* __restrict__ fc_b,
                          float* __restrict__ out)
{
    int b=blockIdx.x;
    int o=threadIdx.x>>5, lane=threadIdx.x&31;
    const float* p=&g_pool[b*512];
    const float* w=&fc_w[o*512];
    float s=0.f;
    #pragma unroll 4
    for(int k=lane;k<512;k+=32) s+=p[k]*w[k];
    #pragma unroll
    for(int off=16;off;off>>=1) s+=__shfl_xor_sync(0xffffffffu,s,off);
    if(lane==0) out[b*2+o]=s+fc_b[o];
}

extern "C" void kernel_launch(void* const* d_in, const int* in_sizes, int n_in,
                              void* d_out, int out_size)
{
    const float* x     =(const float*)d_in[0];
    const float* w_ih0 =(const float*)d_in[1];
    const float* w_hh0 =(const float*)d_in[2];
    const float* b_ih0 =(const float*)d_in[3];
    const float* b_hh0 =(const float*)d_in[4];
    const float* w_ih1 =(const float*)d_in[5];
    const float* w_hh1 =(const float*)d_in[6];
    const float* b_ih1 =(const float*)d_in[7];
    const float* b_hh1 =(const float*)d_in[8];
    const float* fc_w  =(const float*)d_in[9];
    const float* fc_b  =(const float*)d_in[10];
    float* out=(float*)d_out;

    cudaFuncSetAttribute(lstm_scan_kernel<0>, cudaFuncAttributeMaxDynamicSharedMemorySize, SM_TOT);
    cudaFuncSetAttribute(lstm_scan_kernel<1>, cudaFuncAttributeMaxDynamicSharedMemorySize, SM_TOT);
    cudaFuncSetAttribute(gx1_gemm_kernel,     cudaFuncAttributeMaxDynamicSharedMemorySize, GX_SM);

    init_kernel<<<1,96>>>();
    lstm_scan_kernel<0><<<128,256,SM_TOT>>>(x, w_ih0, w_hh0, b_ih0, b_hh0);
    gx1_gemm_kernel<<<dim3(16,512),256,GX_SM>>>(w_ih1);
    lstm_scan_kernel<1><<<128,256,SM_TOT>>>(nullptr, nullptr, w_hh1, b_ih1, b_hh1);
    fc_kernel<<<128,64>>>(fc_w, fc_b, out);
}